// round 11
// baseline (speedup 1.0000x reference)
#include <cuda_runtime.h>
#include <cuda_fp16.h>
#include <cstdint>

#define BATCH 16384
#define CODE  512
#define HID   1024
#define NLAYER 7
#define MBLK  128                 // m-blocks of 128 rows
#define TPL   512                 // tiles per layer (128 m x 4 n)
#define NTILES (NLAYER * TPL)     // 3584
#define GRID  148

// ---------------- static device scratch ----------------
__device__ __half g_W[CODE*HID + 6*CODE*CODE];
__device__ __half g_H[BATCH*HID];
__device__ __half g_V[2][BATCH*CODE];
__device__ unsigned g_epoch;                  // bumped once per launch (cvt_h)
__device__ unsigned g_cnt[NLAYER * MBLK];     // += 4 per launch per cell
__device__ unsigned g_ready[NLAYER * MBLK];   // == epoch when m-block published

// ---------------- helpers ----------------
__device__ __forceinline__ uint32_t smem_u32(const void* p) {
    uint32_t a;
    asm("{ .reg .u64 t; cvta.to.shared.u64 t, %1; cvt.u32.u64 %0, t; }" : "=r"(a) : "l"(p));
    return a;
}
__device__ __forceinline__ void ldsm4(uint32_t* r, uint32_t a) {
    asm volatile("ldmatrix.sync.aligned.m8n8.x4.shared.b16 {%0,%1,%2,%3}, [%4];"
        : "=r"(r[0]), "=r"(r[1]), "=r"(r[2]), "=r"(r[3]) : "r"(a));
}
__device__ __forceinline__ void mma16816(float* d, const uint32_t* a, uint32_t b0, uint32_t b1) {
    asm volatile("mma.sync.aligned.m16n8k16.row.col.f32.f16.f16.f32 "
        "{%0,%1,%2,%3},{%4,%5,%6,%7},{%8,%9},{%0,%1,%2,%3};"
        : "+f"(d[0]), "+f"(d[1]), "+f"(d[2]), "+f"(d[3])
        : "r"(a[0]), "r"(a[1]), "r"(a[2]), "r"(a[3]), "r"(b0), "r"(b1));
}
#define CP_ASYNC(s, g) asm volatile("cp.async.cg.shared.global [%0], [%1], 16;" :: "r"(s), "l"(g))
#define CP_COMMIT()    asm volatile("cp.async.commit_group;")
#define CP_WAIT1()     asm volatile("cp.async.wait_group 1;")

// ---------------- converters ----------------
__global__ void cvt_w(const float4* __restrict__ src, __half2* __restrict__ w, int n4) {
    int i = blockIdx.x * blockDim.x + threadIdx.x;
    if (i >= n4) return;
    float4 v = src[i];
    w[2*i]   = __halves2half2(__float2half_rn(v.x), __float2half_rn(v.y));
    w[2*i+1] = __halves2half2(__float2half_rn(v.z), __float2half_rn(v.w));
}
// hidden convert + per-launch epoch bump
__global__ void cvt_h(const float4* __restrict__ src, __half2* __restrict__ w, int n4) {
    if (blockIdx.x == 0 && threadIdx.x == 0) atomicAdd(&g_epoch, 1u);
    int i = blockIdx.x * blockDim.x + threadIdx.x;
    if (i >= n4) return;
    float4 v = src[i];
    w[2*i]   = __halves2half2(__float2half_rn(v.x), __float2half_rn(v.y));
    w[2*i+1] = __halves2half2(__float2half_rn(v.z), __float2half_rn(v.w));
}

// ---------------- in-kernel Householder for one 128-row m-block ----------------
// 8 warps x 16 rows. __ldcg on v and z (L1 is not coherent across SMs).
__device__ void hh_block(const __half* __restrict__ V,
                         const float* __restrict__ zin, float* __restrict__ zout,
                         int m0, int tid)
{
    const int lane = tid & 31, w = tid >> 5;
    #pragma unroll 1
    for (int rr = 0; rr < 16; rr++) {
        const int row = m0 + w * 16 + rr;
        const uint4*  vp = (const uint4*)(V + (size_t)row * CODE) + 2 * lane;
        const float4* zp = (const float4*)(zin + (size_t)row * CODE) + 4 * lane;
        uint4 u0 = __ldcg(vp), u1 = __ldcg(vp + 1);
        float4 z0 = __ldcg(zp), z1 = __ldcg(zp + 1), z2 = __ldcg(zp + 2), z3 = __ldcg(zp + 3);
        float v[16], z[16];
        const uint32_t* uu = &u0.x;
        #pragma unroll
        for (int j = 0; j < 4; j++) {
            float2 f = __half22float2(*(const __half2*)&uu[j]);
            v[2*j] = f.x; v[2*j+1] = f.y;
        }
        const uint32_t* uv = &u1.x;
        #pragma unroll
        for (int j = 0; j < 4; j++) {
            float2 f = __half22float2(*(const __half2*)&uv[j]);
            v[8+2*j] = f.x; v[8+2*j+1] = f.y;
        }
        z[0]=z0.x; z[1]=z0.y; z[2]=z0.z; z[3]=z0.w;
        z[4]=z1.x; z[5]=z1.y; z[6]=z1.z; z[7]=z1.w;
        z[8]=z2.x; z[9]=z2.y; z[10]=z2.z; z[11]=z2.w;
        z[12]=z3.x; z[13]=z3.y; z[14]=z3.z; z[15]=z3.w;
        float vz = 0.f, vv = 0.f;
        #pragma unroll
        for (int j = 0; j < 16; j++) { vz += v[j] * z[j]; vv += v[j] * v[j]; }
        #pragma unroll
        for (int o = 16; o; o >>= 1) {
            vz += __shfl_xor_sync(0xffffffffu, vz, o);
            vv += __shfl_xor_sync(0xffffffffu, vv, o);
        }
        const float s = 2.f * vz / vv;
        float4* zo = (float4*)(zout + (size_t)row * CODE) + 4 * lane;
        float4 o0, o1, o2, o3;
        o0.x=z[0]-s*v[0];  o0.y=z[1]-s*v[1];  o0.z=z[2]-s*v[2];  o0.w=z[3]-s*v[3];
        o1.x=z[4]-s*v[4];  o1.y=z[5]-s*v[5];  o1.z=z[6]-s*v[6];  o1.w=z[7]-s*v[7];
        o2.x=z[8]-s*v[8];  o2.y=z[9]-s*v[9];  o2.z=z[10]-s*v[10]; o2.w=z[11]-s*v[11];
        o3.x=z[12]-s*v[12]; o3.y=z[13]-s*v[13]; o3.z=z[14]-s*v[14]; o3.w=z[15]-s*v[15];
        zo[0]=o0; zo[1]=o1; zo[2]=o2; zo[3]=o3;
    }
}

// ---------------- persistent megakernel ----------------
// Tiles in global order g = layer*512 + m*4 + n; CTA i takes g = i, i+GRID, ...
// Deps point strictly backward in g  ->  with all GRID CTAs resident, no deadlock.
#define SEC_B    16384
#define STAGE_B  (2 * SEC_B)           // 32768
#define GSMEM    (3 * STAGE_B)         // 98304

__global__ void __launch_bounds__(256)
megak(const __half* __restrict__ Hf, const __half* __restrict__ Wf,
      const float* __restrict__ b0, const float* __restrict__ bs,
      const float* __restrict__ zs, float* __restrict__ out,
      __half* __restrict__ V0, __half* __restrict__ V1)
{
    extern __shared__ char smx[];
    __shared__ int sFlag;
    const uint32_t sb = smem_u32(smx);
    const int tid = threadIdx.x, lane = tid & 31, wid = tid >> 5;
    const int wm = wid & 1, wn = wid >> 1;
    const unsigned E = *(volatile unsigned*)&g_epoch;

    // hoisted thread-constant addressing
    const int lrow = tid >> 3, lc = tid & 7;
    uint32_t sOff[4];
    #pragma unroll
    for (int q = 0; q < 4; q++) {
        int row = lrow + q * 32;
        sOff[q] = (uint32_t)row * 128 + (uint32_t)((lc ^ (row & 7)) << 4);
    }
    int rA[4];
    #pragma unroll
    for (int mt = 0; mt < 4; mt++) rA[mt] = wm * 64 + mt * 16 + (lane & 15);
    const int cA = lane >> 4;
    int nB[2];
    #pragma unroll
    for (int p = 0; p < 2; p++) nB[p] = wn * 32 + p * 16 + (lane & 7) + ((lane >> 4) << 3);
    const int cB = (lane >> 3) & 1;
    const int gid = lane >> 2, qid = lane & 3;

    #pragma unroll 1
    for (int g = blockIdx.x; g < NTILES; g += GRID) {
        const int layer = g >> 9, rem = g & 511, m = rem >> 2, n = rem & 3;
        const int m0 = m * 128, n0 = n * 128;
        const int K = layer ? CODE : HID;
        const int NITER = K >> 6;
        const __half* A  = (layer == 0) ? Hf : (((layer - 1) & 1) ? V1 : V0);
        __half* Vout     = (layer & 1) ? V1 : V0;
        const __half* Wl = (layer == 0) ? Wf
                           : Wf + CODE * HID + (size_t)(layer - 1) * CODE * CODE;
        const float* bias = (layer == 0) ? b0 : bs + (layer - 1) * CODE;

        // ---- dependency wait: input m-block of previous layer published ----
        if (layer > 0) {
            if (tid == 0) {
                volatile unsigned* f = &g_ready[(layer - 1) * MBLK + m];
                while (*f != E) { asm volatile("nanosleep.u32 %0;" :: "r"(128u)); }
                __threadfence();
            }
            __syncthreads();
        }

        // ---- per-tile gmem base addresses ----
        const char* gA = (const char*)A  + (size_t)(m0 + lrow) * (K * 2) + lc * 16;
        const char* gW = (const char*)Wl + (size_t)(n0 + lrow) * (K * 2) + lc * 16;
        const size_t rstep = (size_t)32 * K * 2;

        float bcol[8];
        #pragma unroll
        for (int nt = 0; nt < 4; nt++) {
            const int col = n0 + wn * 32 + nt * 8 + qid * 2;
            bcol[nt * 2]     = __ldg(bias + col);
            bcol[nt * 2 + 1] = __ldg(bias + col + 1);
        }

        float acc[16][4] = {};

        auto prefetch = [&](int it) {
            if (it < NITER) {
                const uint32_t slot = sb + (uint32_t)(it % 3) * STAGE_B;
                const uint32_t koff = (uint32_t)it * 128;
                #pragma unroll
                for (int q = 0; q < 4; q++) {
                    CP_ASYNC(slot + sOff[q],         gA + q * rstep + koff);
                    CP_ASYNC(slot + SEC_B + sOff[q], gW + q * rstep + koff);
                }
            }
            CP_COMMIT();
        };

        prefetch(0);
        prefetch(1);

        #pragma unroll 1
        for (int it = 0; it < NITER; it++) {
            CP_WAIT1();
            __syncthreads();
            prefetch(it + 2);

            const uint32_t slot = sb + (uint32_t)(it % 3) * STAGE_B;
            #pragma unroll
            for (int ks = 0; ks < 4; ks++) {
                uint32_t a[4][4], w[2][4];
                #pragma unroll
                for (int mt = 0; mt < 4; mt++) {
                    const uint32_t ro = (uint32_t)rA[mt] * 128 +
                        (uint32_t)((((ks * 2 + cA) ^ (rA[mt] & 7))) << 4);
                    ldsm4(a[mt], slot + ro);
                }
                #pragma unroll
                for (int p = 0; p < 2; p++) {
                    const uint32_t ro = (uint32_t)nB[p] * 128 +
                        (uint32_t)((((ks * 2 + cB) ^ (nB[p] & 7))) << 4);
                    ldsm4(w[p], slot + SEC_B + ro);
                }
                #pragma unroll
                for (int mt = 0; mt < 4; mt++) {
                    #pragma unroll
                    for (int nt = 0; nt < 4; nt++) {
                        mma16816(acc[mt * 4 + nt], a[mt],
                                 w[nt >> 1][(nt & 1) * 2], w[nt >> 1][(nt & 1) * 2 + 1]);
                    }
                }
            }
        }

        // ---- epilogue: +bias, store v fp16 ----
        #pragma unroll
        for (int mt = 0; mt < 4; mt++) {
            #pragma unroll
            for (int nt = 0; nt < 4; nt++) {
                const float* d = acc[mt * 4 + nt];
                const int row = m0 + wm * 64 + mt * 16 + gid;
                const int col = n0 + wn * 32 + nt * 8 + qid * 2;
                const float a0 = bcol[nt * 2], a1 = bcol[nt * 2 + 1];
                *(__half2*)(Vout + (size_t)row * CODE + col) =
                    __halves2half2(__float2half_rn(d[0] + a0), __float2half_rn(d[1] + a1));
                *(__half2*)(Vout + (size_t)(row + 8) * CODE + col) =
                    __halves2half2(__float2half_rn(d[2] + a0), __float2half_rn(d[3] + a1));
            }
        }

        // ---- completion: release V tile; 4th finisher runs HH and publishes ----
        __syncthreads();
        if (tid == 0) {
            __threadfence();
            unsigned old = atomicAdd(&g_cnt[layer * MBLK + m], 1u);
            sFlag = (old == 4u * E - 1u) ? 1 : 0;
        }
        __syncthreads();
        if (sFlag) {
            hh_block(Vout, (layer == 0) ? zs : out, out, m0, tid);
            __syncthreads();
            if (tid == 0) {
                __threadfence();
                atomicExch(&g_ready[layer * MBLK + m], E);
            }
        }
    }
}

// ---------------- stream/event context (load time; no device mem) ----------------
struct HHCtx {
    cudaStream_t s = nullptr;
    cudaEvent_t fork = nullptr, wdone = nullptr;
    bool ok = false;
    HHCtx() {
        if (cudaStreamCreateWithFlags(&s, cudaStreamNonBlocking) != cudaSuccess) return;
        if (cudaEventCreateWithFlags(&fork,  cudaEventDisableTiming) != cudaSuccess) return;
        if (cudaEventCreateWithFlags(&wdone, cudaEventDisableTiming) != cudaSuccess) return;
        ok = true;
    }
};
static HHCtx g_ctx;

// ---------------- host launch ----------------
extern "C" void kernel_launch(void* const* d_in, const int* in_sizes, int n_in,
                              void* d_out, int out_size)
{
    (void)in_sizes; (void)n_in; (void)out_size;
    const float* hidden = (const float*)d_in[0];
    const float* zs     = (const float*)d_in[1];
    const float* W0     = (const float*)d_in[2];
    const float* b0     = (const float*)d_in[3];
    const float* Ws     = (const float*)d_in[4];
    const float* bs     = (const float*)d_in[5];
    float* out = (float*)d_out;

    void *pW, *pH, *pV;
    cudaGetSymbolAddress(&pW, g_W);
    cudaGetSymbolAddress(&pH, g_H);
    cudaGetSymbolAddress(&pV, g_V);
    __half* Wf = (__half*)pW;
    __half* Hf = (__half*)pH;
    __half* V0 = (__half*)pV;
    __half* V1 = V0 + (size_t)BATCH * CODE;

    cudaFuncSetAttribute(megak, cudaFuncAttributeMaxDynamicSharedMemorySize, GSMEM);

    const int nW0 = CODE * HID, nWs = 6 * CODE * CODE, nH = BATCH * HID;

    const bool fork_ok = g_ctx.ok;
    cudaStream_t sW = fork_ok ? g_ctx.s : (cudaStream_t)0;

    if (fork_ok) {
        cudaEventRecord(g_ctx.fork, 0);
        cudaStreamWaitEvent(g_ctx.s, g_ctx.fork, 0);
    }
    cvt_w<<<(nW0/4 + 255)/256, 256, 0, sW>>>((const float4*)W0, (__half2*)Wf, nW0/4);
    cvt_w<<<(nWs/4 + 255)/256, 256, 0, sW>>>((const float4*)Ws, (__half2*)(Wf + nW0), nWs/4);
    cvt_h<<<(nH/4 + 255)/256, 256>>>((const float4*)hidden, (__half2*)Hf, nH/4);
    if (fork_ok) {
        cudaEventRecord(g_ctx.wdone, g_ctx.s);
        cudaStreamWaitEvent(0, g_ctx.wdone, 0);
    }

    megak<<<GRID, 256, GSMEM>>>(Hf, Wf, b0, bs, zs, out, V0, V1);
}

// round 12
// speedup vs baseline: 1.5123x; 1.5123x over previous
#include <cuda_runtime.h>
#include <cuda_fp16.h>
#include <cstdint>

#define BATCH 16384
#define CODE  512
#define HID   1024
#define NLAYER 7
#define MBLK  128

// ---------------- static device scratch ----------------
__device__ __half g_W[CODE*HID + 6*CODE*CODE];
__device__ __half g_H[BATCH*HID];
__device__ __half g_V[2][BATCH*CODE];
__device__ unsigned g_epoch;                  // bumped once per launch (cvt_h)
__device__ unsigned g_cnt[NLAYER * MBLK];     // += 4 per launch per cell

// ---------------- helpers ----------------
__device__ __forceinline__ uint32_t smem_u32(const void* p) {
    uint32_t a;
    asm("{ .reg .u64 t; cvta.to.shared.u64 t, %1; cvt.u32.u64 %0, t; }" : "=r"(a) : "l"(p));
    return a;
}
__device__ __forceinline__ void ldsm4(uint32_t* r, uint32_t a) {
    asm volatile("ldmatrix.sync.aligned.m8n8.x4.shared.b16 {%0,%1,%2,%3}, [%4];"
        : "=r"(r[0]), "=r"(r[1]), "=r"(r[2]), "=r"(r[3]) : "r"(a));
}
__device__ __forceinline__ void mma16816(float* d, const uint32_t* a, uint32_t b0, uint32_t b1) {
    asm volatile("mma.sync.aligned.m16n8k16.row.col.f32.f16.f16.f32 "
        "{%0,%1,%2,%3},{%4,%5,%6,%7},{%8,%9},{%0,%1,%2,%3};"
        : "+f"(d[0]), "+f"(d[1]), "+f"(d[2]), "+f"(d[3])
        : "r"(a[0]), "r"(a[1]), "r"(a[2]), "r"(a[3]), "r"(b0), "r"(b1));
}
#define CP_ASYNC(s, g) asm volatile("cp.async.cg.shared.global [%0], [%1], 16;" :: "r"(s), "l"(g))
#define CP_COMMIT()    asm volatile("cp.async.commit_group;")
#define CP_WAIT1()     asm volatile("cp.async.wait_group 1;")

// ---------------- converters ----------------
__global__ void cvt_w(const float4* __restrict__ src, __half2* __restrict__ w, int n4) {
    int i = blockIdx.x * blockDim.x + threadIdx.x;
    if (i >= n4) return;
    float4 v = src[i];
    w[2*i]   = __halves2half2(__float2half_rn(v.x), __float2half_rn(v.y));
    w[2*i+1] = __halves2half2(__float2half_rn(v.z), __float2half_rn(v.w));
}
__global__ void cvt_h(const float4* __restrict__ src, __half2* __restrict__ w, int n4) {
    if (blockIdx.x == 0 && threadIdx.x == 0) atomicAdd(&g_epoch, 1u);
    int i = blockIdx.x * blockDim.x + threadIdx.x;
    if (i >= n4) return;
    float4 v = src[i];
    w[2*i]   = __halves2half2(__float2half_rn(v.x), __float2half_rn(v.y));
    w[2*i+1] = __halves2half2(__float2half_rn(v.z), __float2half_rn(v.w));
}

// ---------------- in-kernel Householder for one 128-row m-block ----------------
// 8 warps x 16 rows. __ldcg on v and z (L1 not coherent across SMs).
__device__ void hh_block(const __half* __restrict__ V,
                         const float* __restrict__ zin, float* __restrict__ zout,
                         int m0, int tid)
{
    const int lane = tid & 31, w = tid >> 5;
    #pragma unroll 1
    for (int rr = 0; rr < 16; rr++) {
        const int row = m0 + w * 16 + rr;
        const uint4*  vp = (const uint4*)(V + (size_t)row * CODE) + 2 * lane;
        const float4* zp = (const float4*)(zin + (size_t)row * CODE) + 4 * lane;
        uint4 u0 = __ldcg(vp), u1 = __ldcg(vp + 1);
        float4 z0 = __ldcg(zp), z1 = __ldcg(zp + 1), z2 = __ldcg(zp + 2), z3 = __ldcg(zp + 3);
        float v[16], z[16];
        const uint32_t* uu = &u0.x;
        #pragma unroll
        for (int j = 0; j < 4; j++) {
            float2 f = __half22float2(*(const __half2*)&uu[j]);
            v[2*j] = f.x; v[2*j+1] = f.y;
        }
        const uint32_t* uv = &u1.x;
        #pragma unroll
        for (int j = 0; j < 4; j++) {
            float2 f = __half22float2(*(const __half2*)&uv[j]);
            v[8+2*j] = f.x; v[8+2*j+1] = f.y;
        }
        z[0]=z0.x; z[1]=z0.y; z[2]=z0.z; z[3]=z0.w;
        z[4]=z1.x; z[5]=z1.y; z[6]=z1.z; z[7]=z1.w;
        z[8]=z2.x; z[9]=z2.y; z[10]=z2.z; z[11]=z2.w;
        z[12]=z3.x; z[13]=z3.y; z[14]=z3.z; z[15]=z3.w;
        float vz = 0.f, vv = 0.f;
        #pragma unroll
        for (int j = 0; j < 16; j++) { vz += v[j] * z[j]; vv += v[j] * v[j]; }
        #pragma unroll
        for (int o = 16; o; o >>= 1) {
            vz += __shfl_xor_sync(0xffffffffu, vz, o);
            vv += __shfl_xor_sync(0xffffffffu, vv, o);
        }
        const float s = 2.f * vz / vv;
        float4* zo = (float4*)(zout + (size_t)row * CODE) + 4 * lane;
        float4 o0, o1, o2, o3;
        o0.x=z[0]-s*v[0];  o0.y=z[1]-s*v[1];  o0.z=z[2]-s*v[2];  o0.w=z[3]-s*v[3];
        o1.x=z[4]-s*v[4];  o1.y=z[5]-s*v[5];  o1.z=z[6]-s*v[6];  o1.w=z[7]-s*v[7];
        o2.x=z[8]-s*v[8];  o2.y=z[9]-s*v[9];  o2.z=z[10]-s*v[10]; o2.w=z[11]-s*v[11];
        o3.x=z[12]-s*v[12]; o3.y=z[13]-s*v[13]; o3.z=z[14]-s*v[14]; o3.w=z[15]-s*v[15];
        zo[0]=o0; zo[1]=o1; zo[2]=o2; zo[3]=o3;
    }
}

// ---------------- GEMM + fused HH: V = A @ W^T + bias; 4th n-tile finisher
// of each m-block runs that block's Householder update inline. ----------------
// CTA tile 128x128 (grid 128 x 4), 8 warps of 64x32, k-chunk 64, 3-stage
// cp.async pipeline, 2 CTAs/SM. Stage = A(16K)|W(16K), SW128.
#define SEC_B    16384
#define STAGE_B  (2 * SEC_B)           // 32768
#define GSMEM    (3 * STAGE_B)         // 98304

template<int K>
__global__ void __launch_bounds__(256, 2)
gemm_hh(const __half* __restrict__ A, const __half* __restrict__ W,
        const float* __restrict__ bias, __half* __restrict__ Vout,
        const float* __restrict__ zin, float* __restrict__ zout, int layer)
{
    extern __shared__ char sm[];
    __shared__ int sFlag;
    const uint32_t sb = smem_u32(sm);
    const int tid = threadIdx.x, lane = tid & 31, wid = tid >> 5;
    const int wm = wid & 1, wn = wid >> 1;
    const int m = blockIdx.x, m0 = m * 128, n0 = blockIdx.y * 128;
    constexpr int NITER = K / 64;

    const int lrow = tid >> 3, lc = tid & 7;
    uint32_t sOff[4], gAo[4], gBo[4];
    #pragma unroll
    for (int q = 0; q < 4; q++) {
        int row = lrow + q * 32;
        sOff[q] = (uint32_t)row * 128 + (uint32_t)((lc ^ (row & 7)) << 4);
        gAo[q] = (uint32_t)(m0 + row) * (K * 2) + lc * 16;
        gBo[q] = (uint32_t)(n0 + row) * (K * 2) + lc * 16;
    }

    int rA[4];
    #pragma unroll
    for (int mt = 0; mt < 4; mt++) rA[mt] = wm * 64 + mt * 16 + (lane & 15);
    const int cA = lane >> 4;
    int nB[2];
    #pragma unroll
    for (int p = 0; p < 2; p++) nB[p] = wn * 32 + p * 16 + (lane & 7) + ((lane >> 4) << 3);
    const int cB = (lane >> 3) & 1;

    const int gid = lane >> 2, qid = lane & 3;
    float bcol[8];
    #pragma unroll
    for (int nt = 0; nt < 4; nt++) {
        const int col = n0 + wn * 32 + nt * 8 + qid * 2;
        bcol[nt * 2]     = __ldg(bias + col);
        bcol[nt * 2 + 1] = __ldg(bias + col + 1);
    }

    float acc[16][4] = {};

    auto prefetch = [&](int it) {
        if (it < NITER) {
            const uint32_t slot = sb + (uint32_t)(it % 3) * STAGE_B;
            const uint32_t koff = (uint32_t)it * 128;
            #pragma unroll
            for (int q = 0; q < 4; q++) {
                CP_ASYNC(slot + sOff[q],         (const char*)A + gAo[q] + koff);
                CP_ASYNC(slot + SEC_B + sOff[q], (const char*)W + gBo[q] + koff);
            }
        }
        CP_COMMIT();
    };

    prefetch(0);
    prefetch(1);

    #pragma unroll 1
    for (int it = 0; it < NITER; it++) {
        CP_WAIT1();
        __syncthreads();
        prefetch(it + 2);

        const uint32_t slot = sb + (uint32_t)(it % 3) * STAGE_B;
        #pragma unroll
        for (int ks = 0; ks < 4; ks++) {
            uint32_t a[4][4], w[2][4];
            #pragma unroll
            for (int mt = 0; mt < 4; mt++) {
                const uint32_t ro = (uint32_t)rA[mt] * 128 +
                    (uint32_t)((((ks * 2 + cA) ^ (rA[mt] & 7))) << 4);
                ldsm4(a[mt], slot + ro);
            }
            #pragma unroll
            for (int p = 0; p < 2; p++) {
                const uint32_t ro = (uint32_t)nB[p] * 128 +
                    (uint32_t)((((ks * 2 + cB) ^ (nB[p] & 7))) << 4);
                ldsm4(w[p], slot + SEC_B + ro);
            }
            #pragma unroll
            for (int mt = 0; mt < 4; mt++) {
                #pragma unroll
                for (int nt = 0; nt < 4; nt++) {
                    mma16816(acc[mt * 4 + nt], a[mt],
                             w[nt >> 1][(nt & 1) * 2], w[nt >> 1][(nt & 1) * 2 + 1]);
                }
            }
        }
    }

    // ---- epilogue: +bias, store v fp16 ----
    #pragma unroll
    for (int mt = 0; mt < 4; mt++) {
        #pragma unroll
        for (int nt = 0; nt < 4; nt++) {
            const float* d = acc[mt * 4 + nt];
            const int row = m0 + wm * 64 + mt * 16 + gid;
            const int col = n0 + wn * 32 + nt * 8 + qid * 2;
            const float b0 = bcol[nt * 2], b1 = bcol[nt * 2 + 1];
            *(__half2*)(Vout + (size_t)row * CODE + col) =
                __halves2half2(__float2half_rn(d[0] + b0), __float2half_rn(d[1] + b1));
            *(__half2*)(Vout + (size_t)(row + 8) * CODE + col) =
                __halves2half2(__float2half_rn(d[2] + b0), __float2half_rn(d[3] + b1));
        }
    }

    // ---- 4th finisher of this m-block runs the Householder update ----
    __threadfence();                       // make this CTA's V stores visible
    __syncthreads();
    if (tid == 0) {
        const unsigned E = *(volatile unsigned*)&g_epoch;
        unsigned old = atomicAdd(&g_cnt[layer * MBLK + m], 1u);
        sFlag = (old == 4u * E - 1u) ? 1 : 0;
    }
    __syncthreads();
    if (sFlag) hh_block(Vout, zin, zout, m0, tid);
}

// ---------------- stream/event context (load time; no device mem) ----------------
struct HHCtx {
    cudaStream_t s = nullptr;
    cudaEvent_t fork = nullptr, wdone = nullptr;
    bool ok = false;
    HHCtx() {
        if (cudaStreamCreateWithFlags(&s, cudaStreamNonBlocking) != cudaSuccess) return;
        if (cudaEventCreateWithFlags(&fork,  cudaEventDisableTiming) != cudaSuccess) return;
        if (cudaEventCreateWithFlags(&wdone, cudaEventDisableTiming) != cudaSuccess) return;
        ok = true;
    }
};
static HHCtx g_ctx;

// ---------------- host launch ----------------
extern "C" void kernel_launch(void* const* d_in, const int* in_sizes, int n_in,
                              void* d_out, int out_size)
{
    (void)in_sizes; (void)n_in; (void)out_size;
    const float* hidden = (const float*)d_in[0];
    const float* zs     = (const float*)d_in[1];
    const float* W0     = (const float*)d_in[2];
    const float* b0     = (const float*)d_in[3];
    const float* Ws     = (const float*)d_in[4];
    const float* bs     = (const float*)d_in[5];
    float* out = (float*)d_out;

    void *pW, *pH, *pV;
    cudaGetSymbolAddress(&pW, g_W);
    cudaGetSymbolAddress(&pH, g_H);
    cudaGetSymbolAddress(&pV, g_V);
    __half* Wf = (__half*)pW;
    __half* Hf = (__half*)pH;
    __half* V0 = (__half*)pV;
    __half* V1 = V0 + (size_t)BATCH * CODE;

    cudaFuncSetAttribute(gemm_hh<HID>,  cudaFuncAttributeMaxDynamicSharedMemorySize, GSMEM);
    cudaFuncSetAttribute(gemm_hh<CODE>, cudaFuncAttributeMaxDynamicSharedMemorySize, GSMEM);

    const int nW0 = CODE * HID, nWs = 6 * CODE * CODE, nH = BATCH * HID;
    const dim3 ggrid(BATCH / 128, CODE / 128);   // 128 x 4

    const bool fork_ok = g_ctx.ok;
    cudaStream_t sW = fork_ok ? g_ctx.s : (cudaStream_t)0;

    if (fork_ok) {
        cudaEventRecord(g_ctx.fork, 0);
        cudaStreamWaitEvent(g_ctx.s, g_ctx.fork, 0);
    }
    cvt_w<<<(nW0/4 + 255)/256, 256, 0, sW>>>((const float4*)W0, (__half2*)Wf, nW0/4);
    cvt_w<<<(nWs/4 + 255)/256, 256, 0, sW>>>((const float4*)Ws, (__half2*)(Wf + nW0), nWs/4);
    cvt_h<<<(nH/4 + 255)/256, 256>>>((const float4*)hidden, (__half2*)Hf, nH/4);
    if (fork_ok) {
        cudaEventRecord(g_ctx.wdone, g_ctx.s);
        cudaStreamWaitEvent(0, g_ctx.wdone, 0);
    }

    // layer 0: v = hidden @ W0^T + b0 ; HH fused (zs -> out)
    gemm_hh<HID><<<ggrid, 256, GSMEM>>>(Hf, Wf, b0, V0, zs, out, 0);

    // layers 1..6: v = v @ Ws^T + bs ; HH fused (out -> out)
    __half *cur = V0, *nxt = V1;
    for (int l = 1; l <= 6; l++) {
        const __half* Wl = Wf + nW0 + (size_t)(l - 1) * CODE * CODE;
        gemm_hh<CODE><<<ggrid, 256, GSMEM>>>(cur, Wl, bs + (l - 1) * CODE, nxt, out, out, l);
        __half* t = cur; cur = nxt; nxt = t;
    }
}

// round 13
// speedup vs baseline: 3.3273x; 2.2002x over previous
#include <cuda_runtime.h>
#include <cuda_fp16.h>
#include <cstdint>

#define BATCH 16384
#define CODE  512
#define HID   1024
#define NCHAIN 4
#define CROWS (BATCH / NCHAIN)        // 4096 rows per chain

// ---------------- static device scratch ----------------
__device__ __half g_W[CODE*HID + 6*CODE*CODE];
__device__ __half g_H[BATCH*HID];
__device__ __half g_V[3][BATCH*CODE];    // 3-buffer rotation (no WAR race)

// ---------------- helpers ----------------
__device__ __forceinline__ uint32_t smem_u32(const void* p) {
    uint32_t a;
    asm("{ .reg .u64 t; cvta.to.shared.u64 t, %1; cvt.u32.u64 %0, t; }" : "=r"(a) : "l"(p));
    return a;
}
__device__ __forceinline__ void ldsm4(uint32_t* r, uint32_t a) {
    asm volatile("ldmatrix.sync.aligned.m8n8.x4.shared.b16 {%0,%1,%2,%3}, [%4];"
        : "=r"(r[0]), "=r"(r[1]), "=r"(r[2]), "=r"(r[3]) : "r"(a));
}
__device__ __forceinline__ void mma16816(float* d, const uint32_t* a, uint32_t b0, uint32_t b1) {
    asm volatile("mma.sync.aligned.m16n8k16.row.col.f32.f16.f16.f32 "
        "{%0,%1,%2,%3},{%4,%5,%6,%7},{%8,%9},{%0,%1,%2,%3};"
        : "+f"(d[0]), "+f"(d[1]), "+f"(d[2]), "+f"(d[3])
        : "r"(a[0]), "r"(a[1]), "r"(a[2]), "r"(a[3]), "r"(b0), "r"(b1));
}
#define CP_ASYNC(s, g) asm volatile("cp.async.cg.shared.global [%0], [%1], 16;" :: "r"(s), "l"(g))
#define CP_COMMIT()    asm volatile("cp.async.commit_group;")
#define CP_WAIT1()     asm volatile("cp.async.wait_group 1;")

// ---------------- converter: fp32 -> fp16 ----------------
__global__ void cvt_h(const float4* __restrict__ src, __half2* __restrict__ w, int n4) {
    int i = blockIdx.x * blockDim.x + threadIdx.x;
    if (i >= n4) return;
    float4 v = src[i];
    w[2*i]   = __halves2half2(__float2half_rn(v.x), __float2half_rn(v.y));
    w[2*i+1] = __halves2half2(__float2half_rn(v.z), __float2half_rn(v.w));
}

// ---------------- GEMM: V = A @ W^T + bias, fp16 single-pass ----------------
// CTA tile 128x128, 8 warps of 64x32, k-chunk 64, 3-stage cp.async pipeline,
// 2 CTAs/SM. Stage = A(16K)|W(16K), SW128 swizzle. (Unchanged from R10.)
#define SEC_B    16384
#define STAGE_B  (2 * SEC_B)           // 32768
#define GSMEM    (3 * STAGE_B)         // 98304

template<int K>
__global__ void __launch_bounds__(256, 2)
gemm_layer(const __half* __restrict__ A, const __half* __restrict__ W,
           const float* __restrict__ bias, __half* __restrict__ Vout)
{
    extern __shared__ char sm[];
    const uint32_t sb = smem_u32(sm);
    const int tid = threadIdx.x, lane = tid & 31, wid = tid >> 5;
    const int wm = wid & 1, wn = wid >> 1;            // 2 x 4 warp grid
    const int m0 = blockIdx.x * 128, n0 = blockIdx.y * 128;
    constexpr int NITER = K / 64;

    const int lrow = tid >> 3, lc = tid & 7;
    uint32_t sOff[4], gAo[4], gBo[4];
    #pragma unroll
    for (int q = 0; q < 4; q++) {
        int row = lrow + q * 32;
        sOff[q] = (uint32_t)row * 128 + (uint32_t)((lc ^ (row & 7)) << 4);
        gAo[q] = (uint32_t)(m0 + row) * (K * 2) + lc * 16;
        gBo[q] = (uint32_t)(n0 + row) * (K * 2) + lc * 16;
    }

    int rA[4];
    #pragma unroll
    for (int mt = 0; mt < 4; mt++) rA[mt] = wm * 64 + mt * 16 + (lane & 15);
    const int cA = lane >> 4;
    int nB[2];
    #pragma unroll
    for (int p = 0; p < 2; p++) nB[p] = wn * 32 + p * 16 + (lane & 7) + ((lane >> 4) << 3);
    const int cB = (lane >> 3) & 1;

    const int gid = lane >> 2, qid = lane & 3;
    float bcol[8];
    #pragma unroll
    for (int nt = 0; nt < 4; nt++) {
        const int col = n0 + wn * 32 + nt * 8 + qid * 2;
        bcol[nt * 2]     = __ldg(bias + col);
        bcol[nt * 2 + 1] = __ldg(bias + col + 1);
    }

    float acc[16][4] = {};

    auto prefetch = [&](int it) {
        if (it < NITER) {
            const uint32_t slot = sb + (uint32_t)(it % 3) * STAGE_B;
            const uint32_t koff = (uint32_t)it * 128;
            #pragma unroll
            for (int q = 0; q < 4; q++) {
                CP_ASYNC(slot + sOff[q],         (const char*)A + gAo[q] + koff);
                CP_ASYNC(slot + SEC_B + sOff[q], (const char*)W + gBo[q] + koff);
            }
        }
        CP_COMMIT();
    };

    prefetch(0);
    prefetch(1);

    #pragma unroll 1
    for (int it = 0; it < NITER; it++) {
        CP_WAIT1();
        __syncthreads();
        prefetch(it + 2);

        const uint32_t slot = sb + (uint32_t)(it % 3) * STAGE_B;
        #pragma unroll
        for (int ks = 0; ks < 4; ks++) {
            uint32_t a[4][4], w[2][4];
            #pragma unroll
            for (int mt = 0; mt < 4; mt++) {
                const uint32_t ro = (uint32_t)rA[mt] * 128 +
                    (uint32_t)((((ks * 2 + cA) ^ (rA[mt] & 7))) << 4);
                ldsm4(a[mt], slot + ro);
            }
            #pragma unroll
            for (int p = 0; p < 2; p++) {
                const uint32_t ro = (uint32_t)nB[p] * 128 +
                    (uint32_t)((((ks * 2 + cB) ^ (nB[p] & 7))) << 4);
                ldsm4(w[p], slot + SEC_B + ro);
            }
            #pragma unroll
            for (int mt = 0; mt < 4; mt++) {
                #pragma unroll
                for (int nt = 0; nt < 4; nt++) {
                    mma16816(acc[mt * 4 + nt], a[mt],
                             w[nt >> 1][(nt & 1) * 2], w[nt >> 1][(nt & 1) * 2 + 1]);
                }
            }
        }
    }

    #pragma unroll
    for (int mt = 0; mt < 4; mt++) {
        #pragma unroll
        for (int nt = 0; nt < 4; nt++) {
            const float* d = acc[mt * 4 + nt];
            const int row = m0 + wm * 64 + mt * 16 + gid;
            const int col = n0 + wn * 32 + nt * 8 + qid * 2;
            const float b0 = bcol[nt * 2], b1 = bcol[nt * 2 + 1];
            *(__half2*)(Vout + (size_t)row * CODE + col) =
                __halves2half2(__float2half_rn(d[0] + b0), __float2half_rn(d[1] + b1));
            *(__half2*)(Vout + (size_t)(row + 8) * CODE + col) =
                __halves2half2(__float2half_rn(d[2] + b0), __float2half_rn(d[3] + b1));
        }
    }
}

// ---------------- Householder: z -= 2 v (v.z)/(v.v), one warp per row ----------------
__global__ void __launch_bounds__(256)
hh_kernel(const __half* __restrict__ V,
          const float* __restrict__ z_in, float* __restrict__ z_out)
{
    const int lane = threadIdx.x & 31, warp = threadIdx.x >> 5;
    const size_t row = (size_t)blockIdx.x * 8 + warp;
    const __half* vp = V + row * CODE;
    const float* zi = z_in + row * CODE;

    float v[16], z[16];
    float vz = 0.f, vv = 0.f;
    #pragma unroll
    for (int ch = 0; ch < 4; ch++) {
        const int c = ch * 128 + lane * 4;
        uint2 hp = *(const uint2*)(vp + c);
        float4 zt = *(const float4*)(zi + c);
        float2 h0 = __half22float2(*(const __half2*)&hp.x);
        float2 h1 = __half22float2(*(const __half2*)&hp.y);
        v[ch*4+0] = h0.x; v[ch*4+1] = h0.y; v[ch*4+2] = h1.x; v[ch*4+3] = h1.y;
        z[ch*4+0] = zt.x; z[ch*4+1] = zt.y; z[ch*4+2] = zt.z; z[ch*4+3] = zt.w;
        #pragma unroll
        for (int j = 0; j < 4; j++) {
            vz += v[ch*4+j] * z[ch*4+j];
            vv += v[ch*4+j] * v[ch*4+j];
        }
    }
    #pragma unroll
    for (int o = 16; o; o >>= 1) {
        vz += __shfl_xor_sync(0xffffffffu, vz, o);
        vv += __shfl_xor_sync(0xffffffffu, vv, o);
    }
    const float s = 2.f * vz / vv;
    float* zo = z_out + row * CODE;
    #pragma unroll
    for (int ch = 0; ch < 4; ch++) {
        const int c = ch * 128 + lane * 4;
        float4 o;
        o.x = z[ch*4+0] - s * v[ch*4+0];
        o.y = z[ch*4+1] - s * v[ch*4+1];
        o.z = z[ch*4+2] - s * v[ch*4+2];
        o.w = z[ch*4+3] - s * v[ch*4+3];
        *(float4*)(zo + c) = o;
    }
}

// ---------------- stream/event context (load time; no device mem) ----------------
struct HHCtx {
    cudaStream_t sg[NCHAIN] = {}, sh[NCHAIN] = {};
    cudaEvent_t fork = nullptr, evW = nullptr;
    cudaEvent_t evG[NCHAIN][7] = {};
    cudaEvent_t evH[NCHAIN] = {};
    bool ok = false;
    HHCtx() {
        for (int c = 0; c < NCHAIN; c++) {
            if (cudaStreamCreateWithFlags(&sg[c], cudaStreamNonBlocking) != cudaSuccess) return;
            if (cudaStreamCreateWithFlags(&sh[c], cudaStreamNonBlocking) != cudaSuccess) return;
        }
        if (cudaEventCreateWithFlags(&fork, cudaEventDisableTiming) != cudaSuccess) return;
        if (cudaEventCreateWithFlags(&evW,  cudaEventDisableTiming) != cudaSuccess) return;
        for (int c = 0; c < NCHAIN; c++) {
            for (int l = 0; l < 7; l++)
                if (cudaEventCreateWithFlags(&evG[c][l], cudaEventDisableTiming) != cudaSuccess) return;
            if (cudaEventCreateWithFlags(&evH[c], cudaEventDisableTiming) != cudaSuccess) return;
        }
        ok = true;
    }
};
static HHCtx g_ctx;

// ---------------- host launch ----------------
extern "C" void kernel_launch(void* const* d_in, const int* in_sizes, int n_in,
                              void* d_out, int out_size)
{
    (void)in_sizes; (void)n_in; (void)out_size;
    const float* hidden = (const float*)d_in[0];
    const float* zs     = (const float*)d_in[1];
    const float* W0     = (const float*)d_in[2];
    const float* b0     = (const float*)d_in[3];
    const float* Ws     = (const float*)d_in[4];
    const float* bs     = (const float*)d_in[5];
    float* out = (float*)d_out;

    void *pW, *pH, *pV;
    cudaGetSymbolAddress(&pW, g_W);
    cudaGetSymbolAddress(&pH, g_H);
    cudaGetSymbolAddress(&pV, g_V);
    __half* Wf = (__half*)pW;
    __half* Hf = (__half*)pH;
    __half* Vb[3];
    Vb[0] = (__half*)pV;
    Vb[1] = Vb[0] + (size_t)BATCH * CODE;
    Vb[2] = Vb[1] + (size_t)BATCH * CODE;

    cudaFuncSetAttribute(gemm_layer<HID>,  cudaFuncAttributeMaxDynamicSharedMemorySize, GSMEM);
    cudaFuncSetAttribute(gemm_layer<CODE>, cudaFuncAttributeMaxDynamicSharedMemorySize, GSMEM);

    const int nW0 = CODE * HID, nWs = 6 * CODE * CODE;
    const int nHq = CROWS * HID;                  // per-chain hidden elements
    const dim3 ggrid(CROWS / 128, CODE / 128);    // 32 x 4 per chain
    const int hgrid = CROWS / 8;                  // 512 per chain

    if (!g_ctx.ok) {
        // fallback: fully serial on the capture stream (correct, slower)
        cvt_h<<<(nW0/4 + 255)/256, 256>>>((const float4*)W0, (__half2*)Wf, nW0/4);
        cvt_h<<<(nWs/4 + 255)/256, 256>>>((const float4*)Ws, (__half2*)(Wf + nW0), nWs/4);
        cvt_h<<<(BATCH*HID/4 + 255)/256, 256>>>((const float4*)hidden, (__half2*)Hf, BATCH*HID/4);
        for (int c = 0; c < NCHAIN; c++) {
            const size_t ho = (size_t)c * CROWS * HID, vo = (size_t)c * CROWS * CODE;
            const size_t zo = (size_t)c * CROWS * CODE;
            gemm_layer<HID><<<ggrid, 256, GSMEM>>>(Hf + ho, Wf, b0, Vb[0] + vo);
            hh_kernel<<<hgrid, 256>>>(Vb[0] + vo, zs + zo, out + zo);
            for (int l = 1; l <= 6; l++) {
                gemm_layer<CODE><<<ggrid, 256, GSMEM>>>(Vb[(l-1)%3] + vo,
                    Wf + nW0 + (size_t)(l-1)*CODE*CODE, bs + (l-1)*CODE, Vb[l%3] + vo);
                hh_kernel<<<hgrid, 256>>>(Vb[l%3] + vo, out + zo, out + zo);
            }
        }
        return;
    }

    // fork all streams off the capture stream
    cudaEventRecord(g_ctx.fork, 0);
    for (int c = 0; c < NCHAIN; c++) {
        cudaStreamWaitEvent(g_ctx.sg[c], g_ctx.fork, 0);
        cudaStreamWaitEvent(g_ctx.sh[c], g_ctx.fork, 0);
    }

    // weights on sg[0]; other chains wait on evW
    cvt_h<<<(nW0/4 + 255)/256, 256, 0, g_ctx.sg[0]>>>((const float4*)W0, (__half2*)Wf, nW0/4);
    cvt_h<<<(nWs/4 + 255)/256, 256, 0, g_ctx.sg[0]>>>((const float4*)Ws, (__half2*)(Wf + nW0), nWs/4);
    cudaEventRecord(g_ctx.evW, g_ctx.sg[0]);
    for (int c = 1; c < NCHAIN; c++)
        cudaStreamWaitEvent(g_ctx.sg[c], g_ctx.evW, 0);

    // per-chain hidden convert
    for (int c = 0; c < NCHAIN; c++) {
        cvt_h<<<(nHq/4 + 255)/256, 256, 0, g_ctx.sg[c]>>>(
            (const float4*)(hidden + (size_t)c * nHq), (__half2*)(Hf + (size_t)c * nHq), nHq/4);
    }

    // layer-major launch order across chains (encourages desync/packing)
    for (int l = 0; l < 7; l++) {
        for (int c = 0; c < NCHAIN; c++) {
            const size_t vo = (size_t)c * CROWS * CODE;
            const size_t zo = (size_t)c * CROWS * CODE;
            if (l == 0) {
                gemm_layer<HID><<<ggrid, 256, GSMEM, g_ctx.sg[c]>>>(
                    Hf + (size_t)c * nHq, Wf, b0, Vb[0] + vo);
            } else {
                gemm_layer<CODE><<<ggrid, 256, GSMEM, g_ctx.sg[c]>>>(
                    Vb[(l-1)%3] + vo, Wf + nW0 + (size_t)(l-1)*CODE*CODE,
                    bs + (l-1)*CODE, Vb[l%3] + vo);
            }
            cudaEventRecord(g_ctx.evG[c][l], g_ctx.sg[c]);
            cudaStreamWaitEvent(g_ctx.sh[c], g_ctx.evG[c][l], 0);
            hh_kernel<<<hgrid, 256, 0, g_ctx.sh[c]>>>(
                Vb[l%3] + vo, (l == 0) ? zs + zo : out + zo, out + zo);
        }
    }

    // join: capture stream waits for every chain's hh tail
    for (int c = 0; c < NCHAIN; c++) {
        cudaEventRecord(g_ctx.evH[c], g_ctx.sh[c]);
        cudaStreamWaitEvent(0, g_ctx.evH[c], 0);
    }
}